// round 2
// baseline (speedup 1.0000x reference)
#include <cuda_runtime.h>

// ContrastiveLoss: B=16384, D=256, N_CLASSES=1000
// loss = -(1/B) * sum_b [ dot(Tn_b,Sn_b) - log( sum_{c: lab_c != lab_b} exp(Tn_b . Sn_c) ) ]
// NOTE: labels arrive as int32 (JAX x64 disabled downgrades the declared int64).

#define NB 16384
#define D 256
#define COL_TILES 128   // 16384 / 128

// -------- scratch (device globals: no allocation allowed) --------
__device__ float g_Tn[(size_t)NB * D];                 // 16 MB
__device__ float g_Sn[(size_t)NB * D];                 // 16 MB
__device__ float g_diag[NB];
__device__ int   g_lab[NB];
__device__ float g_negpart[(size_t)NB * COL_TILES];    // 8 MB  [row][colTile]
__device__ float g_partial[64];

// ---------------------------------------------------------------
// Kernel 1: normalize rows of T and S, compute diag dot, copy labels.
// One block (256 threads) per row.
// ---------------------------------------------------------------
__global__ void k_norm(const float* __restrict__ T,
                       const float* __restrict__ S,
                       const int* __restrict__ lab) {
    int row = blockIdx.x;
    int tid = threadIdx.x;
    size_t base = (size_t)row * D + tid;
    float t = T[base];
    float s = S[base];
    float tt = t * t, ss = s * s, ts = t * s;
    #pragma unroll
    for (int o = 16; o; o >>= 1) {
        tt += __shfl_xor_sync(0xffffffffu, tt, o);
        ss += __shfl_xor_sync(0xffffffffu, ss, o);
        ts += __shfl_xor_sync(0xffffffffu, ts, o);
    }
    __shared__ float stt[8], sss[8], sts[8];
    int w = tid >> 5;
    if ((tid & 31) == 0) { stt[w] = tt; sss[w] = ss; sts[w] = ts; }
    __syncthreads();
    float TT = 0.f, SS = 0.f, TS = 0.f;
    #pragma unroll
    for (int i = 0; i < 8; i++) { TT += stt[i]; SS += sss[i]; TS += sts[i]; }
    float nT = fmaxf(sqrtf(TT), 1e-8f);
    float nS = fmaxf(sqrtf(SS), 1e-8f);
    g_Tn[base] = t / nT;
    g_Sn[base] = s / nS;
    if (tid == 0) {
        g_diag[row] = TS / (nT * nS);
        g_lab[row]  = lab[row];
    }
}

// ---------------------------------------------------------------
// Kernel 2: fused GEMM (Tn . Sn^T) + exp + label-mask + row partial sums.
// Block computes a 128x128 tile with K=256; 256 threads, 8x8 micro-tile.
// Deterministic: each block writes its own g_negpart[row][colTile] slot.
// ---------------------------------------------------------------
__global__ __launch_bounds__(256, 2) void k_gemm() {
    __shared__ float As[128][17];
    __shared__ float Bs[128][17];
    __shared__ int   labR[128];
    __shared__ int   labC[128];
    __shared__ float red[16][128];

    const int tid = threadIdx.x;
    const int rowBase = blockIdx.y * 128;
    const int colBase = blockIdx.x * 128;

    const int lane = tid & 31, warp = tid >> 5;
    const int wr = lane >> 3, wc = lane & 7;   // 4 x 8 within warp
    const int wy = warp >> 1, wx = warp & 1;   // 4 x 2 warps
    const int rgrp = wy * 4 + wr;              // 0..15 -> rows rgrp*8..+7
    const int cgrp = wx * 8 + wc;              // 0..15 -> cols cgrp*8..+7

    if (tid < 128) labR[tid] = g_lab[rowBase + tid];
    else           labC[tid - 128] = g_lab[colBase + tid - 128];

    // load mapping: 512 float4 slots per tile per matrix, 2 per thread
    const int p0 = tid, p1 = tid + 256;
    const int r0 = p0 >> 2, kq0 = p0 & 3;
    const int r1 = p1 >> 2, kq1 = p1 & 3;
    const float* Abase0 = g_Tn + (size_t)(rowBase + r0) * D + kq0 * 4;
    const float* Abase1 = g_Tn + (size_t)(rowBase + r1) * D + kq1 * 4;
    const float* Bbase0 = g_Sn + (size_t)(colBase + r0) * D + kq0 * 4;
    const float* Bbase1 = g_Sn + (size_t)(colBase + r1) * D + kq1 * 4;

    float acc[8][8];
    #pragma unroll
    for (int r = 0; r < 8; r++)
        #pragma unroll
        for (int c = 0; c < 8; c++) acc[r][c] = 0.f;

    float4 pa0 = *(const float4*)(Abase0);
    float4 pa1 = *(const float4*)(Abase1);
    float4 pb0 = *(const float4*)(Bbase0);
    float4 pb1 = *(const float4*)(Bbase1);

    #pragma unroll 1
    for (int kt = 0; kt < 16; kt++) {
        __syncthreads();
        As[r0][kq0 * 4 + 0] = pa0.x; As[r0][kq0 * 4 + 1] = pa0.y;
        As[r0][kq0 * 4 + 2] = pa0.z; As[r0][kq0 * 4 + 3] = pa0.w;
        As[r1][kq1 * 4 + 0] = pa1.x; As[r1][kq1 * 4 + 1] = pa1.y;
        As[r1][kq1 * 4 + 2] = pa1.z; As[r1][kq1 * 4 + 3] = pa1.w;
        Bs[r0][kq0 * 4 + 0] = pb0.x; Bs[r0][kq0 * 4 + 1] = pb0.y;
        Bs[r0][kq0 * 4 + 2] = pb0.z; Bs[r0][kq0 * 4 + 3] = pb0.w;
        Bs[r1][kq1 * 4 + 0] = pb1.x; Bs[r1][kq1 * 4 + 1] = pb1.y;
        Bs[r1][kq1 * 4 + 2] = pb1.z; Bs[r1][kq1 * 4 + 3] = pb1.w;
        __syncthreads();

        if (kt < 15) {
            int k0 = (kt + 1) * 16;
            pa0 = *(const float4*)(Abase0 + k0);
            pa1 = *(const float4*)(Abase1 + k0);
            pb0 = *(const float4*)(Bbase0 + k0);
            pb1 = *(const float4*)(Bbase1 + k0);
        }

        #pragma unroll
        for (int k = 0; k < 16; k++) {
            float a[8], b[8];
            #pragma unroll
            for (int j = 0; j < 8; j++) a[j] = As[rgrp * 8 + j][k];
            #pragma unroll
            for (int j = 0; j < 8; j++) b[j] = Bs[cgrp * 8 + j][k];
            #pragma unroll
            for (int r = 0; r < 8; r++)
                #pragma unroll
                for (int c = 0; c < 8; c++)
                    acc[r][c] = fmaf(a[r], b[c], acc[r][c]);
        }
    }

    // epilogue: exp + mask + per-thread row sums
    int lr[8], lc[8];
    #pragma unroll
    for (int j = 0; j < 8; j++) { lr[j] = labR[rgrp * 8 + j]; lc[j] = labC[cgrp * 8 + j]; }

    float rsum[8];
    #pragma unroll
    for (int r = 0; r < 8; r++) {
        float rs = 0.f;
        #pragma unroll
        for (int c = 0; c < 8; c++) {
            float ev = __expf(acc[r][c]);
            rs += (lr[r] != lc[c]) ? ev : 0.f;
        }
        rsum[r] = rs;
    }

    // reduce across the 16 column-groups via shared, write unique slot
    #pragma unroll
    for (int j = 0; j < 8; j++) red[cgrp][rgrp * 8 + j] = rsum[j];
    __syncthreads();
    if (tid < 128) {
        float s = 0.f;
        #pragma unroll
        for (int g = 0; g < 16; g++) s += red[g][tid];
        g_negpart[(size_t)(rowBase + tid) * COL_TILES + blockIdx.x] = s;
    }
}

// ---------------------------------------------------------------
// Kernel 3: per-row finalize (sum 128 partials, diag - log) + block partials.
// 64 blocks x 256 threads covering 16384 rows.
// ---------------------------------------------------------------
__global__ void k_rowfinal() {
    int idx = blockIdx.x * 256 + threadIdx.x;
    const float4* p = (const float4*)(g_negpart + (size_t)idx * COL_TILES);
    float ns = 0.f;
    #pragma unroll
    for (int i = 0; i < 32; i++) {
        float4 v = p[i];
        ns += (v.x + v.y) + (v.z + v.w);
    }
    float val = g_diag[idx] - logf(ns);
    #pragma unroll
    for (int o = 16; o; o >>= 1) val += __shfl_xor_sync(0xffffffffu, val, o);
    __shared__ float sw[8];
    if ((threadIdx.x & 31) == 0) sw[threadIdx.x >> 5] = val;
    __syncthreads();
    if (threadIdx.x == 0) {
        float s = 0.f;
        #pragma unroll
        for (int i = 0; i < 8; i++) s += sw[i];
        g_partial[blockIdx.x] = s;
    }
}

// Kernel 4: final scalar
__global__ void k_final(float* __restrict__ out) {
    float v = g_partial[threadIdx.x];  // 64 threads
    #pragma unroll
    for (int o = 16; o; o >>= 1) v += __shfl_xor_sync(0xffffffffu, v, o);
    __shared__ float sw[2];
    if ((threadIdx.x & 31) == 0) sw[threadIdx.x >> 5] = v;
    __syncthreads();
    if (threadIdx.x == 0) out[0] = -(sw[0] + sw[1]) / (float)NB;
}

// ---------------------------------------------------------------
extern "C" void kernel_launch(void* const* d_in, const int* in_sizes, int n_in,
                              void* d_out, int out_size) {
    (void)in_sizes; (void)n_in; (void)out_size;
    const float* T   = (const float*)d_in[0];
    const float* S   = (const float*)d_in[1];
    const int*   lab = (const int*)d_in[2];
    float* out = (float*)d_out;

    k_norm<<<NB, 256>>>(T, S, lab);
    dim3 grid(COL_TILES, NB / 128);
    k_gemm<<<grid, 256>>>();
    k_rowfinal<<<64, 256>>>();
    k_final<<<1, 64>>>(out);
}

// round 6
// speedup vs baseline: 9.0584x; 9.0584x over previous
#include <cuda_runtime.h>
#include <cuda_bf16.h>
#include <cstdint>

// ContrastiveLoss: B=16384, D=256
// loss = -(1/B) * sum_b [ dot(Tn_b,Sn_b) - log( sum_{c: lab_c != lab_b} exp(Tn_b . Sn_c) ) ]
// R6: bf16 mma.sync GEMM, K-chunked into static SMEM (<48KB) — removes the
// cudaFuncSetAttribute/dynamic-SMEM opt-in that correlated with container failures.

#define NB 16384
#define D 256
#define TM 128
#define TN 128
#define CT (NB / TN)        // 128 col tiles
#define KC 64               // K chunk
#define LDT 72              // bf16 per SMEM row (64 + 8 pad) -> conflict-free ldmatrix

// -------- scratch (device globals: no allocation allowed) --------
__device__ __nv_bfloat16 g_Tb[(size_t)NB * D];      // 8 MB
__device__ __nv_bfloat16 g_Sb[(size_t)NB * D];      // 8 MB
__device__ float g_diag[NB];
__device__ int   g_lab[NB];
__device__ float g_negpart[(size_t)NB * CT];        // 8 MB
__device__ float g_partial[64];

__device__ __forceinline__ uint32_t smem_u32(const void* p) {
    uint32_t a;
    asm("{ .reg .u64 t; cvta.to.shared.u64 t, %1; cvt.u32.u64 %0, t; }" : "=r"(a) : "l"(p));
    return a;
}
__device__ __forceinline__ void ldm_x4(uint32_t& r0, uint32_t& r1, uint32_t& r2, uint32_t& r3,
                                       uint32_t addr) {
    asm volatile("ldmatrix.sync.aligned.m8n8.x4.shared.b16 {%0,%1,%2,%3}, [%4];"
                 : "=r"(r0), "=r"(r1), "=r"(r2), "=r"(r3) : "r"(addr));
}
__device__ __forceinline__ void mma16816(float* d, const uint32_t* a, uint32_t b0, uint32_t b1) {
    asm volatile(
        "mma.sync.aligned.m16n8k16.row.col.f32.bf16.bf16.f32 "
        "{%0,%1,%2,%3}, {%4,%5,%6,%7}, {%8,%9}, {%0,%1,%2,%3};"
        : "+f"(d[0]), "+f"(d[1]), "+f"(d[2]), "+f"(d[3])
        : "r"(a[0]), "r"(a[1]), "r"(a[2]), "r"(a[3]), "r"(b0), "r"(b1));
}

// ---------------------------------------------------------------
// Kernel 1: normalize rows (bf16 out), diag dot (fp32), labels.
// ---------------------------------------------------------------
__global__ void k_norm(const float* __restrict__ T,
                       const float* __restrict__ S,
                       const int* __restrict__ lab) {
    int row = blockIdx.x;
    int tid = threadIdx.x;
    size_t base = (size_t)row * D + tid;
    float t = T[base];
    float s = S[base];
    float tt = t * t, ss = s * s, ts = t * s;
    #pragma unroll
    for (int o = 16; o; o >>= 1) {
        tt += __shfl_xor_sync(0xffffffffu, tt, o);
        ss += __shfl_xor_sync(0xffffffffu, ss, o);
        ts += __shfl_xor_sync(0xffffffffu, ts, o);
    }
    __shared__ float stt[8], sss[8], sts[8];
    int w = tid >> 5;
    if ((tid & 31) == 0) { stt[w] = tt; sss[w] = ss; sts[w] = ts; }
    __syncthreads();
    float TT = 0.f, SS = 0.f, TS = 0.f;
    #pragma unroll
    for (int i = 0; i < 8; i++) { TT += stt[i]; SS += sss[i]; TS += sts[i]; }
    float nT = fmaxf(sqrtf(TT), 1e-8f);
    float nS = fmaxf(sqrtf(SS), 1e-8f);
    g_Tb[base] = __float2bfloat16(t / nT);
    g_Sb[base] = __float2bfloat16(s / nS);
    if (tid == 0) {
        g_diag[row] = TS / (nT * nS);
        g_lab[row]  = lab[row];
    }
}

// ---------------------------------------------------------------
// Kernel 2: 128x128 tile GEMM via mma.sync, K chunked 4 x 64.
// 256 threads = 8 warps (2 x 4); warp tile 64x32 (4x4 m16n8k16 frags).
// Static SMEM only (~40 KB).
// ---------------------------------------------------------------
__global__ __launch_bounds__(256, 2) void k_gemm() {
    __shared__ __nv_bfloat16 sA[TM * LDT];    // 18432 B
    __shared__ __nv_bfloat16 sB[TN * LDT];    // 18432 B
    __shared__ int   labR[128];
    __shared__ int   labC[128];
    __shared__ float red[4][128];

    const int tid = threadIdx.x;
    const int l = tid & 31, w = tid >> 5;
    const int wy = w >> 2, wx = w & 3;
    const int rowBase = blockIdx.y * TM;
    const int colBase = blockIdx.x * TN;

    if (tid < 128) labR[tid] = g_lab[rowBase + tid];
    else           labC[tid - 128] = g_lab[colBase + tid - 128];

    const uint4* srcA = (const uint4*)(g_Tb + (size_t)rowBase * D);
    const uint4* srcB = (const uint4*)(g_Sb + (size_t)colBase * D);

    // ldmatrix lane address bases
    // A: rows (l&15), col-block (l>>4)*8  -> a0..a3 frag order
    // B: rows ((l>>4)&1)*8 + (l&7), col-block ((l>>3)&1)*8
    uint32_t aAddr = smem_u32(sA + (wy * 64 + (l & 15)) * LDT + (l >> 4) * 8);
    uint32_t bAddr = smem_u32(sB + (wx * 32 + ((l >> 4) & 1) * 8 + (l & 7)) * LDT
                              + ((l >> 3) & 1) * 8);

    float acc[4][4][4];
    #pragma unroll
    for (int mi = 0; mi < 4; mi++)
        #pragma unroll
        for (int ni = 0; ni < 4; ni++)
            #pragma unroll
            for (int k = 0; k < 4; k++) acc[mi][ni][k] = 0.f;

    #pragma unroll 1
    for (int ck = 0; ck < 4; ck++) {
        __syncthreads();   // previous chunk fully consumed
        // load chunk: 128 rows x 8 uint4 (64 bf16) each matrix; 4 uint4/thread
        #pragma unroll
        for (int i = 0; i < 4; i++) {
            int idx = i * 256 + tid;        // 1024 slots
            int r = idx >> 3, q = idx & 7;
            *(uint4*)(sA + r * LDT + q * 8) = srcA[(size_t)r * 32 + ck * 8 + q];
            *(uint4*)(sB + r * LDT + q * 8) = srcB[(size_t)r * 32 + ck * 8 + q];
        }
        __syncthreads();

        #pragma unroll
        for (int ks = 0; ks < 4; ks++) {
            uint32_t a[4][4], b[2][4];
            #pragma unroll
            for (int mi = 0; mi < 4; mi++)
                ldm_x4(a[mi][0], a[mi][1], a[mi][2], a[mi][3],
                       aAddr + (uint32_t)(mi * 16 * LDT + ks * 16) * 2u);
            #pragma unroll
            for (int j = 0; j < 2; j++)
                ldm_x4(b[j][0], b[j][1], b[j][2], b[j][3],
                       bAddr + (uint32_t)(j * 16 * LDT + ks * 16) * 2u);
            #pragma unroll
            for (int mi = 0; mi < 4; mi++)
                #pragma unroll
                for (int ni = 0; ni < 4; ni++)
                    mma16816(acc[mi][ni], a[mi],
                             b[ni >> 1][(ni & 1) * 2], b[ni >> 1][(ni & 1) * 2 + 1]);
        }
    }
    __syncthreads();

    // ---- epilogue: exp + label mask + row sums (registers) ----
    int lr0[4], lr1[4];
    #pragma unroll
    for (int mi = 0; mi < 4; mi++) {
        lr0[mi] = labR[wy * 64 + mi * 16 + (l >> 2)];
        lr1[mi] = labR[wy * 64 + mi * 16 + (l >> 2) + 8];
    }
    int lc0[4], lc1[4];
    #pragma unroll
    for (int ni = 0; ni < 4; ni++) {
        int c = wx * 32 + ni * 8 + (l & 3) * 2;
        lc0[ni] = labC[c];
        lc1[ni] = labC[c + 1];
    }

    float sLo[4], sHi[4];
    #pragma unroll
    for (int mi = 0; mi < 4; mi++) { sLo[mi] = 0.f; sHi[mi] = 0.f; }
    #pragma unroll
    for (int mi = 0; mi < 4; mi++)
        #pragma unroll
        for (int ni = 0; ni < 4; ni++) {
            float e0 = __expf(acc[mi][ni][0]);
            float e1 = __expf(acc[mi][ni][1]);
            float e2 = __expf(acc[mi][ni][2]);
            float e3 = __expf(acc[mi][ni][3]);
            sLo[mi] += (lr0[mi] != lc0[ni]) ? e0 : 0.f;
            sLo[mi] += (lr0[mi] != lc1[ni]) ? e1 : 0.f;
            sHi[mi] += (lr1[mi] != lc0[ni]) ? e2 : 0.f;
            sHi[mi] += (lr1[mi] != lc1[ni]) ? e3 : 0.f;
        }
    #pragma unroll
    for (int mi = 0; mi < 4; mi++) {
        sLo[mi] += __shfl_xor_sync(0xffffffffu, sLo[mi], 1);
        sLo[mi] += __shfl_xor_sync(0xffffffffu, sLo[mi], 2);
        sHi[mi] += __shfl_xor_sync(0xffffffffu, sHi[mi], 1);
        sHi[mi] += __shfl_xor_sync(0xffffffffu, sHi[mi], 2);
    }
    if ((l & 3) == 0) {
        int q = l >> 2;
        #pragma unroll
        for (int mi = 0; mi < 4; mi++) {
            red[wx][wy * 64 + mi * 16 + q]     = sLo[mi];
            red[wx][wy * 64 + mi * 16 + q + 8] = sHi[mi];
        }
    }
    __syncthreads();
    if (tid < 128) {
        float s = red[0][tid] + red[1][tid] + red[2][tid] + red[3][tid];
        g_negpart[(size_t)(rowBase + tid) * CT + blockIdx.x] = s;
    }
}

// ---------------------------------------------------------------
// Kernel 3: per-row finalize (sum 128 partials, diag - log) + block partials.
// ---------------------------------------------------------------
__global__ void k_rowfinal() {
    int idx = blockIdx.x * 256 + threadIdx.x;
    const float4* p = (const float4*)(g_negpart + (size_t)idx * CT);
    float ns = 0.f;
    #pragma unroll
    for (int i = 0; i < CT / 4; i++) {
        float4 v = p[i];
        ns += (v.x + v.y) + (v.z + v.w);
    }
    float val = g_diag[idx] - logf(ns);
    #pragma unroll
    for (int o = 16; o; o >>= 1) val += __shfl_xor_sync(0xffffffffu, val, o);
    __shared__ float sw[8];
    if ((threadIdx.x & 31) == 0) sw[threadIdx.x >> 5] = val;
    __syncthreads();
    if (threadIdx.x == 0) {
        float s = 0.f;
        #pragma unroll
        for (int i = 0; i < 8; i++) s += sw[i];
        g_partial[blockIdx.x] = s;
    }
}

// Kernel 4: final scalar
__global__ void k_final(float* __restrict__ out) {
    float v = g_partial[threadIdx.x];  // 64 threads
    #pragma unroll
    for (int o = 16; o; o >>= 1) v += __shfl_xor_sync(0xffffffffu, v, o);
    __shared__ float sw[2];
    if ((threadIdx.x & 31) == 0) sw[threadIdx.x >> 5] = v;
    __syncthreads();
    if (threadIdx.x == 0) out[0] = -(sw[0] + sw[1]) / (float)NB;
}

// ---------------------------------------------------------------
extern "C" void kernel_launch(void* const* d_in, const int* in_sizes, int n_in,
                              void* d_out, int out_size) {
    (void)in_sizes; (void)n_in; (void)out_size;
    const float* T   = (const float*)d_in[0];
    const float* S   = (const float*)d_in[1];
    const int*   lab = (const int*)d_in[2];
    float* out = (float*)d_out;

    k_norm<<<NB, 256>>>(T, S, lab);
    dim3 grid(NB / TN, NB / TM);
    k_gemm<<<grid, 256>>>();
    k_rowfinal<<<64, 256>>>();
    k_final<<<1, 64>>>(out);
}